// round 1
// baseline (speedup 1.0000x reference)
#include <cuda_runtime.h>
#include <math.h>

#define Bn 2
#define HH 256
#define WWD 256
#define HW (HH*WWD)          // 65536
#define VD 256
#define NHEAD 8
#define NTOK 64
#define SCALE 0.35355339059327373f   // 8^-0.5

// ---------------- scratch (device globals; no allocation allowed) ----------------
__device__ __align__(128) float g_Wcat[128*64];                 // [Wq ; Wk@Wq]
__device__ __align__(128) float g_qk  [(size_t)Bn*128*HW];      // qp(0..63), kp(64..127)
__device__ __align__(128) float g_vp  [(size_t)Bn*VD*HW];
__device__ __align__(128) float g_attn[(size_t)Bn*VD*HW];
__device__ __align__(128) float g_dw  [(size_t)Bn*VD*HW];

// ---------------- prep: Wcat = [Wq ; Wk@Wq] ----------------
__global__ void prep_kernel(const float* __restrict__ Wq, const float* __restrict__ Wk) {
    for (int idx = threadIdx.x; idx < 128*64; idx += 256) {
        int o = idx >> 6, i = idx & 63;
        if (o < 64) {
            g_Wcat[idx] = Wq[o*64 + i];
        } else {
            int oo = o - 64;
            float s = 0.f;
            #pragma unroll 8
            for (int c = 0; c < 64; c++) s += Wk[oo*64 + c] * Wq[c*64 + i];
            g_Wcat[idx] = s;
        }
    }
}

// ---------------- generic fp32 SGEMM: Y[b][m][n] = sum_k W[m][k] * X[b][k][n] ----------------
// tiles 128x128, BK=8, 256 threads, 8x8 per-thread microtile
template<int K, int M>
__device__ __forceinline__ void sgemm_body(const float* __restrict__ Wg,
                                           const float* __restrict__ Xg,
                                           float* __restrict__ Yg) {
    __shared__ float Ws[8][128];
    __shared__ float Xs[8][128];
    const int n0 = blockIdx.x * 128;
    const int m0 = blockIdx.y * 128;
    const float* X = Xg + (size_t)blockIdx.z * K * HW;
    float*       Y = Yg + (size_t)blockIdx.z * M * HW;
    const int tid = threadIdx.x;

    const int wm = tid >> 1;            // 0..127
    const int wk = (tid & 1) * 4;       // 0 / 4
    const int xk = tid >> 5;            // 0..7
    const int xn = (tid & 31) * 4;
    const int ty = tid >> 4;            // 0..15 (m)
    const int tx = tid & 15;            // 0..15 (n)

    float acc[8][8];
    #pragma unroll
    for (int i = 0; i < 8; i++)
        #pragma unroll
        for (int j = 0; j < 8; j++) acc[i][j] = 0.f;

    for (int k0 = 0; k0 < K; k0 += 8) {
        float4 w4 = *(const float4*)(Wg + (size_t)(m0 + wm)*K + k0 + wk);
        float4 x4 = *(const float4*)(X  + (size_t)(k0 + xk)*HW + n0 + xn);
        __syncthreads();
        Ws[wk+0][wm] = w4.x; Ws[wk+1][wm] = w4.y; Ws[wk+2][wm] = w4.z; Ws[wk+3][wm] = w4.w;
        *(float4*)(&Xs[xk][xn]) = x4;
        __syncthreads();
        #pragma unroll
        for (int k = 0; k < 8; k++) {
            float a[8], b[8];
            #pragma unroll
            for (int i = 0; i < 8; i++) a[i] = Ws[k][ty*8 + i];
            #pragma unroll
            for (int j = 0; j < 8; j++) b[j] = Xs[k][tx*8 + j];
            #pragma unroll
            for (int i = 0; i < 8; i++)
                #pragma unroll
                for (int j = 0; j < 8; j++) acc[i][j] += a[i] * b[j];
        }
    }
    #pragma unroll
    for (int i = 0; i < 8; i++) {
        float4 v0 = make_float4(acc[i][0], acc[i][1], acc[i][2], acc[i][3]);
        float4 v1 = make_float4(acc[i][4], acc[i][5], acc[i][6], acc[i][7]);
        float* yp = Y + (size_t)(m0 + ty*8 + i)*HW + n0 + tx*8;
        *(float4*)yp       = v0;
        *(float4*)(yp + 4) = v1;
    }
}

__global__ void k_qkp(const float* __restrict__ q) { sgemm_body<64, 128>(g_Wcat, q, g_qk); }
__global__ void k_vp (const float* __restrict__ Wv, const float* __restrict__ v) { sgemm_body<256, 256>(Wv, v, g_vp); }
__global__ void k_pw (const float* __restrict__ pw, float* __restrict__ out)     { sgemm_body<256, 256>(pw, g_dw, out); }

// ---------------- windowed attention: one block per 8x8 window ----------------
// smem: qp[64*65] kp[64*65] vp[256*66] attn[4][64*66]
#define ATTN_SMEM ((64*65*2 + 256*66 + 4*64*66) * 4)

__global__ void attn_kernel(const float* __restrict__ bias_table,
                            const int*   __restrict__ rel_index) {
    extern __shared__ float sm[];
    float* qp_s = sm;
    float* kp_s = qp_s + 64*65;
    float* vp_s = kp_s + 64*65;          // [c*66 + t]
    float* at_s = vp_s + 256*66;         // 4 heads of [n*66 + m]

    const int tid = threadIdx.x;
    const int w  = blockIdx.x;
    const int b  = w >> 10;
    const int wy = (w >> 5) & 31;
    const int wx = w & 31;
    const int y0 = wy * 8, x0 = wx * 8;

    // gather qp / kp windows
    for (int idx = tid; idx < 128*64; idx += 256) {
        int c = idx >> 6, t = idx & 63;
        int y = y0 + (t >> 3), x = x0 + (t & 7);
        float val = g_qk[(((size_t)b*128 + c)*HH + y)*WWD + x];
        if (c < 64) qp_s[t*65 + c]       = val;
        else        kp_s[t*65 + (c-64)]  = val;
    }
    // gather vp window
    for (int idx = tid; idx < 256*64; idx += 256) {
        int c = idx >> 6, t = idx & 63;
        int y = y0 + (t >> 3), x = x0 + (t & 7);
        vp_s[c*66 + t] = g_vp[(((size_t)b*VD + c)*HH + y)*WWD + x];
    }
    __syncthreads();

    const int hid = tid >> 6;     // 0..3 (head within pair-group)
    const int s   = tid & 63;

    for (int hp = 0; hp < 2; hp++) {
        const int h = hp*4 + hid;
        float* A = at_s + hid * (64*66);

        // ---- dots: 8x8 register tile per thread ----
        {
            const int nb = (s >> 3) * 8;
            const int mb = (s & 7) * 8;
            float acc[8][8];
            #pragma unroll
            for (int i = 0; i < 8; i++)
                #pragma unroll
                for (int j = 0; j < 8; j++) acc[i][j] = 0.f;
            #pragma unroll
            for (int d = 0; d < 8; d++) {
                float qn[8], km[8];
                #pragma unroll
                for (int i = 0; i < 8; i++) qn[i] = qp_s[(nb+i)*65 + h*8 + d];
                #pragma unroll
                for (int j = 0; j < 8; j++) km[j] = kp_s[(mb+j)*65 + h*8 + d];
                #pragma unroll
                for (int i = 0; i < 8; i++)
                    #pragma unroll
                    for (int j = 0; j < 8; j++) acc[i][j] += qn[i] * km[j];
            }
            #pragma unroll
            for (int i = 0; i < 8; i++)
                #pragma unroll
                for (int j = 0; j < 8; j++) {
                    int ri = rel_index[(nb+i)*64 + (mb+j)];
                    A[(nb+i)*66 + (mb+j)] = acc[i][j]*SCALE + bias_table[ri*NHEAD + h];
                }
        }
        __syncthreads();

        // ---- softmax: one row per thread (256 threads = 4 heads x 64 rows) ----
        {
            float* Ar = A + s*66;
            float mx = -1e30f;
            #pragma unroll 8
            for (int m = 0; m < 64; m++) mx = fmaxf(mx, Ar[m]);
            float sum = 0.f;
            #pragma unroll 8
            for (int m = 0; m < 64; m++) { float e = __expf(Ar[m] - mx); Ar[m] = e; sum += e; }
            float inv = 1.f / sum;
            #pragma unroll 8
            for (int m = 0; m < 64; m++) Ar[m] *= inv;
        }
        __syncthreads();

        // ---- out = attn @ vp : 8n x 4dv register tile per thread ----
        {
            const int nb  = (s >> 3) * 8;
            const int dvb = (s & 7) * 4;
            float acc[8][4];
            #pragma unroll
            for (int i = 0; i < 8; i++)
                #pragma unroll
                for (int j = 0; j < 4; j++) acc[i][j] = 0.f;
            #pragma unroll 4
            for (int m = 0; m < 64; m++) {
                float an[8], vv[4];
                #pragma unroll
                for (int i = 0; i < 8; i++) an[i] = A[(nb+i)*66 + m];
                #pragma unroll
                for (int j = 0; j < 4; j++) vv[j] = vp_s[(h*32 + dvb + j)*66 + m];
                #pragma unroll
                for (int i = 0; i < 8; i++)
                    #pragma unroll
                    for (int j = 0; j < 4; j++) acc[i][j] += an[i] * vv[j];
            }
            // tokens nb..nb+7 share row r = nb/8, cc = i -> 8 consecutive x
            const int y = y0 + (nb >> 3);
            #pragma unroll
            for (int j = 0; j < 4; j++) {
                int ch = h*32 + dvb + j;
                float* op = &g_attn[(((size_t)b*VD + ch)*HH + y)*WWD + x0];
                #pragma unroll
                for (int i = 0; i < 8; i++) op[i] = acc[i][j];
            }
        }
        __syncthreads();
    }
}

// ---------------- depthwise 8x8 conv (reflect-pad semantics) + BN fold ----------------
__global__ void dw_fn(const float* __restrict__ dwk,
                      const float* __restrict__ gamma, const float* __restrict__ beta,
                      const float* __restrict__ mean,  const float* __restrict__ var) {
    __shared__ float in_s[71*73];
    __shared__ float k_s[64];
    const int tid = threadIdx.x;
    const int c = blockIdx.y;
    const int b = blockIdx.z;
    const int ty0 = (blockIdx.x >> 2) * 64;
    const int tx0 = (blockIdx.x & 3) * 64;

    if (tid < 64) k_s[tid] = dwk[c*64 + tid];
    const float* Ain = g_attn + ((size_t)b*VD + c)*HW;
    for (int idx = tid; idx < 71*71; idx += 256) {
        int ly = idx / 71, lx = idx - ly*71;
        int u  = ty0 - 3 + ly;
        int vv = tx0 - 3 + lx;
        float val = 0.f;
        if (u >= 0 && u <= 256 && vv >= 0 && vv <= 256) {
            int uu = (u  == 256) ? 254 : u;    // reflect pad by 1 (jnp 'reflect')
            int vx = (vv == 256) ? 254 : vv;
            val = Ain[uu*WWD + vx];
        }
        in_s[ly*73 + lx] = val;
    }
    __syncthreads();

    const float inv = gamma[c] * rsqrtf(var[c] + 1e-5f);
    const float sh  = beta[c] - mean[c]*inv;

    const int tx = tid & 7;       // 8 x-groups of 8
    const int ty = tid >> 3;      // 0..31 -> 2 output rows each
    const int ox = tx * 8;
    const int oy = ty * 2;

    float acc0[8], acc1[8];
    #pragma unroll
    for (int x = 0; x < 8; x++) { acc0[x] = 0.f; acc1[x] = 0.f; }

    #pragma unroll
    for (int iy = 0; iy < 9; iy++) {
        float row[15];
        #pragma unroll
        for (int j = 0; j < 15; j++) row[j] = in_s[(oy + iy)*73 + ox + j];
        if (iy < 8) {
            #pragma unroll
            for (int kj = 0; kj < 8; kj++) {
                float kv = k_s[iy*8 + kj];
                #pragma unroll
                for (int x = 0; x < 8; x++) acc0[x] += row[x + kj] * kv;
            }
        }
        if (iy >= 1) {
            #pragma unroll
            for (int kj = 0; kj < 8; kj++) {
                float kv = k_s[(iy-1)*8 + kj];
                #pragma unroll
                for (int x = 0; x < 8; x++) acc1[x] += row[x + kj] * kv;
            }
        }
    }
    float* Out = g_dw + ((size_t)b*VD + c)*HW;
    #pragma unroll
    for (int x = 0; x < 8; x++) Out[(ty0 + oy    )*WWD + tx0 + ox + x] = acc0[x]*inv + sh;
    #pragma unroll
    for (int x = 0; x < 8; x++) Out[(ty0 + oy + 1)*WWD + tx0 + ox + x] = acc1[x]*inv + sh;
}

// ---------------- launch ----------------
extern "C" void kernel_launch(void* const* d_in, const int* in_sizes, int n_in,
                              void* d_out, int out_size) {
    const float* q     = (const float*)d_in[0];
    const float* v     = (const float*)d_in[1];
    const float* Wq    = (const float*)d_in[2];
    const float* Wk    = (const float*)d_in[3];
    const float* Wv    = (const float*)d_in[4];
    const float* bias  = (const float*)d_in[5];
    const float* dwk   = (const float*)d_in[6];
    const float* gamma = (const float*)d_in[7];
    const float* beta  = (const float*)d_in[8];
    const float* mean  = (const float*)d_in[9];
    const float* var   = (const float*)d_in[10];
    const float* pw    = (const float*)d_in[11];
    const int*   rel   = (const int*)d_in[12];
    float* out = (float*)d_out;

    cudaFuncSetAttribute(attn_kernel, cudaFuncAttributeMaxDynamicSharedMemorySize, ATTN_SMEM);

    prep_kernel<<<1, 256>>>(Wq, Wk);
    k_qkp<<<dim3(512, 1, 2), 256>>>(q);
    k_vp <<<dim3(512, 2, 2), 256>>>(Wv, v);
    attn_kernel<<<2048, 256, ATTN_SMEM>>>(bias, rel);
    dw_fn<<<dim3(16, 256, 2), 256>>>(dwk, gamma, beta, mean, var);
    k_pw <<<dim3(512, 2, 2), 256>>>(pw, out);
}